// round 8
// baseline (speedup 1.0000x reference)
#include <cuda_runtime.h>

// GLRFast forward: out[b,g,c,h,w] = patchs - sum_e ew[b,g,e,h,w] * nbr_e(patchs)
// nbr order (DELTAS): e0=(-1,0) up, e1=(0,-1) left, e2=(0,1) right, e3=(1,0) down
// Replicate ('edge') padding on H and W borders.
// Shapes: B=4, G=8, C=32, H=128, W=128 (fp32). node_degree (d_in[2]) unused.

#define H_DIM 128
#define W_DIM 128
#define C_DIM 32
#define ROWS_PER_BLOCK 8
#define C_PER_BLOCK 8

__global__ __launch_bounds__(256) void glrfast_kernel(
    const float* __restrict__ patchs,
    const float* __restrict__ ew,
    float* __restrict__ out)
{
    const int lane = threadIdx.x;                         // 0..31 -> one full row per warp
    const int h    = blockIdx.x * ROWS_PER_BLOCK + threadIdx.y;
    const int c0   = blockIdx.y * C_PER_BLOCK;
    const int bg   = blockIdx.z;                          // 0..31 (= b*G + g)
    const int w0   = lane * 4;

    const int HW = H_DIM * W_DIM;

    // Edge weights for this pixel quad: [bg, e, h, w0..w0+3]
    const float* ewb = ew + ((long)bg * 4) * HW + (long)h * W_DIM + w0;
    const float4 eN = *(const float4*)(ewb + 0L * HW);
    const float4 eW = *(const float4*)(ewb + 1L * HW);
    const float4 eE = *(const float4*)(ewb + 2L * HW);
    const float4 eS = *(const float4*)(ewb + 3L * HW);

    const int hu = (h > 0)         ? h - 1 : 0;           // replicate pad
    const int hd = (h < H_DIM - 1) ? h + 1 : H_DIM - 1;

    const float* pb = patchs + ((long)bg * C_DIM + c0) * HW;
    float*       ob = out    + ((long)bg * C_DIM + c0) * HW;

    const long off_c  = (long)h  * W_DIM + w0;
    const long off_u  = (long)hu * W_DIM + w0;
    const long off_d  = (long)hd * W_DIM + w0;

#pragma unroll
    for (int cc = 0; cc < C_PER_BLOCK; ++cc) {
        const float* pc = pb + (long)cc * HW;

        const float4 cen = *(const float4*)(pc + off_c);
        const float4 up  = *(const float4*)(pc + off_u);
        const float4 dn  = *(const float4*)(pc + off_d);

        // w-direction neighbors via in-warp shuffles (warp == one row)
        float xm1 = __shfl_up_sync(0xffffffffu, cen.w, 1);   // x[w0-1]
        if (lane == 0)  xm1 = cen.x;                          // replicate x[0]
        float xp4 = __shfl_down_sync(0xffffffffu, cen.x, 1); // x[w0+4]
        if (lane == 31) xp4 = cen.w;                          // replicate x[127]

        float4 o;
        o.x = cen.x - (eN.x * up.x + eW.x * xm1   + eE.x * cen.y + eS.x * dn.x);
        o.y = cen.y - (eN.y * up.y + eW.y * cen.x + eE.y * cen.z + eS.y * dn.y);
        o.z = cen.z - (eN.z * up.z + eW.z * cen.y + eE.z * cen.w + eS.z * dn.z);
        o.w = cen.w - (eN.w * up.w + eW.w * cen.z + eE.w * xp4   + eS.w * dn.w);

        *(float4*)(ob + (long)cc * HW + off_c) = o;
    }
}

extern "C" void kernel_launch(void* const* d_in, const int* in_sizes, int n_in,
                              void* d_out, int out_size)
{
    const float* patchs = (const float*)d_in[0];   // [4,8,32,128,128]
    const float* ew     = (const float*)d_in[1];   // [4,8,4,128,128]
    // d_in[2] = node_degree: unused in forward
    float* out = (float*)d_out;                    // [4,8,32,128,128]

    dim3 block(32, ROWS_PER_BLOCK);                           // 256 threads
    dim3 grid(H_DIM / ROWS_PER_BLOCK,                         // 16 h-tiles
              C_DIM / C_PER_BLOCK,                            // 4 c-chunks
              32);                                            // B*G planes

    glrfast_kernel<<<grid, block>>>(patchs, ew, out);
}

// round 9
// speedup vs baseline: 1.0011x; 1.0011x over previous
#include <cuda_runtime.h>

// GLRFast forward: out[b,g,c,h,w] = patchs - sum_e ew[b,g,e,h,w] * nbr_e(patchs)
// nbr order (DELTAS): e0=(-1,0) up, e1=(0,-1) left, e2=(0,1) right, e3=(1,0) down
// Replicate ('edge') padding on H and W borders.
// Shapes: B=4, G=8, C=32, H=128, W=128 (fp32). node_degree (d_in[2]) unused.

#define H_DIM 128
#define W_DIM 128
#define C_DIM 32
#define ROWS_PER_BLOCK 8
#define C_PER_BLOCK 8

__global__ __launch_bounds__(256) void glrfast_kernel(
    const float* __restrict__ patchs,
    const float* __restrict__ ew,
    float* __restrict__ out)
{
    const int lane = threadIdx.x;                         // 0..31 -> one full row per warp
    const int h    = blockIdx.x * ROWS_PER_BLOCK + threadIdx.y;
    const int c0   = blockIdx.y * C_PER_BLOCK;
    const int bg   = blockIdx.z;                          // 0..31 (= b*G + g)
    const int w0   = lane * 4;

    const int HW = H_DIM * W_DIM;

    // Edge weights for this pixel quad: [bg, e, h, w0..w0+3]
    const float* ewb = ew + ((long)bg * 4) * HW + (long)h * W_DIM + w0;
    const float4 eN = *(const float4*)(ewb + 0L * HW);
    const float4 eW = *(const float4*)(ewb + 1L * HW);
    const float4 eE = *(const float4*)(ewb + 2L * HW);
    const float4 eS = *(const float4*)(ewb + 3L * HW);

    const int hu = (h > 0)         ? h - 1 : 0;           // replicate pad
    const int hd = (h < H_DIM - 1) ? h + 1 : H_DIM - 1;

    const float* pb = patchs + ((long)bg * C_DIM + c0) * HW;
    float*       ob = out    + ((long)bg * C_DIM + c0) * HW;

    const long off_c  = (long)h  * W_DIM + w0;
    const long off_u  = (long)hu * W_DIM + w0;
    const long off_d  = (long)hd * W_DIM + w0;

#pragma unroll
    for (int cc = 0; cc < C_PER_BLOCK; ++cc) {
        const float* pc = pb + (long)cc * HW;

        const float4 cen = *(const float4*)(pc + off_c);
        const float4 up  = *(const float4*)(pc + off_u);
        const float4 dn  = *(const float4*)(pc + off_d);

        // w-direction neighbors via in-warp shuffles (warp == one row)
        float xm1 = __shfl_up_sync(0xffffffffu, cen.w, 1);   // x[w0-1]
        if (lane == 0)  xm1 = cen.x;                          // replicate x[0]
        float xp4 = __shfl_down_sync(0xffffffffu, cen.x, 1); // x[w0+4]
        if (lane == 31) xp4 = cen.w;                          // replicate x[127]

        float4 o;
        o.x = cen.x - (eN.x * up.x + eW.x * xm1   + eE.x * cen.y + eS.x * dn.x);
        o.y = cen.y - (eN.y * up.y + eW.y * cen.x + eE.y * cen.z + eS.y * dn.y);
        o.z = cen.z - (eN.z * up.z + eW.z * cen.y + eE.z * cen.w + eS.z * dn.z);
        o.w = cen.w - (eN.w * up.w + eW.w * cen.z + eE.w * xp4   + eS.w * dn.w);

        *(float4*)(ob + (long)cc * HW + off_c) = o;
    }
}

extern "C" void kernel_launch(void* const* d_in, const int* in_sizes, int n_in,
                              void* d_out, int out_size)
{
    const float* patchs = (const float*)d_in[0];   // [4,8,32,128,128]
    const float* ew     = (const float*)d_in[1];   // [4,8,4,128,128]
    // d_in[2] = node_degree: unused in forward
    float* out = (float*)d_out;                    // [4,8,32,128,128]

    dim3 block(32, ROWS_PER_BLOCK);                           // 256 threads
    dim3 grid(H_DIM / ROWS_PER_BLOCK,                         // 16 h-tiles
              C_DIM / C_PER_BLOCK,                            // 4 c-chunks
              32);                                            // B*G planes

    glrfast_kernel<<<grid, block>>>(patchs, ew, out);
}

// round 10
// speedup vs baseline: 1.0099x; 1.0088x over previous
#include <cuda_runtime.h>

// GLRFast forward: out[b,g,c,h,w] = patchs - sum_e ew[b,g,e,h,w] * nbr_e(patchs)
// nbr order (DELTAS): e0=(-1,0) up, e1=(0,-1) left, e2=(0,1) right, e3=(1,0) down
// Replicate ('edge') padding on H and W borders.
// Shapes: B=4, G=8, C=32, H=128, W=128 (fp32). node_degree (d_in[2]) unused.

#define H_DIM 128
#define W_DIM 128
#define C_DIM 32
#define ROWS_PER_BLOCK 8
#define C_PER_BLOCK 8

__global__ __launch_bounds__(256) void glrfast_kernel(
    const float* __restrict__ patchs,
    const float* __restrict__ ew,
    float* __restrict__ out)
{
    const int lane = threadIdx.x;                         // 0..31 -> one full row per warp
    const int h    = blockIdx.x * ROWS_PER_BLOCK + threadIdx.y;
    const int c0   = blockIdx.y * C_PER_BLOCK;
    const int bg   = blockIdx.z;                          // 0..31 (= b*G + g)
    const int w0   = lane * 4;

    const int HW = H_DIM * W_DIM;

    // Edge weights for this pixel quad: [bg, e, h, w0..w0+3]
    const float* ewb = ew + ((long)bg * 4) * HW + (long)h * W_DIM + w0;
    const float4 eN = *(const float4*)(ewb + 0L * HW);
    const float4 eW = *(const float4*)(ewb + 1L * HW);
    const float4 eE = *(const float4*)(ewb + 2L * HW);
    const float4 eS = *(const float4*)(ewb + 3L * HW);

    const int hu = (h > 0)         ? h - 1 : 0;           // replicate pad
    const int hd = (h < H_DIM - 1) ? h + 1 : H_DIM - 1;

    const float* pb = patchs + ((long)bg * C_DIM + c0) * HW;
    float*       ob = out    + ((long)bg * C_DIM + c0) * HW;

    const long off_c  = (long)h  * W_DIM + w0;
    const long off_u  = (long)hu * W_DIM + w0;
    const long off_d  = (long)hd * W_DIM + w0;

#pragma unroll
    for (int cc = 0; cc < C_PER_BLOCK; ++cc) {
        const float* pc = pb + (long)cc * HW;

        const float4 cen = *(const float4*)(pc + off_c);
        const float4 up  = *(const float4*)(pc + off_u);
        const float4 dn  = *(const float4*)(pc + off_d);

        // w-direction neighbors via in-warp shuffles (warp == one row)
        float xm1 = __shfl_up_sync(0xffffffffu, cen.w, 1);   // x[w0-1]
        if (lane == 0)  xm1 = cen.x;                          // replicate x[0]
        float xp4 = __shfl_down_sync(0xffffffffu, cen.x, 1); // x[w0+4]
        if (lane == 31) xp4 = cen.w;                          // replicate x[127]

        float4 o;
        o.x = cen.x - (eN.x * up.x + eW.x * xm1   + eE.x * cen.y + eS.x * dn.x);
        o.y = cen.y - (eN.y * up.y + eW.y * cen.x + eE.y * cen.z + eS.y * dn.y);
        o.z = cen.z - (eN.z * up.z + eW.z * cen.y + eE.z * cen.w + eS.z * dn.z);
        o.w = cen.w - (eN.w * up.w + eW.w * cen.z + eE.w * xp4   + eS.w * dn.w);

        *(float4*)(ob + (long)cc * HW + off_c) = o;
    }
}

extern "C" void kernel_launch(void* const* d_in, const int* in_sizes, int n_in,
                              void* d_out, int out_size)
{
    const float* patchs = (const float*)d_in[0];   // [4,8,32,128,128]
    const float* ew     = (const float*)d_in[1];   // [4,8,4,128,128]
    // d_in[2] = node_degree: unused in forward
    float* out = (float*)d_out;                    // [4,8,32,128,128]

    dim3 block(32, ROWS_PER_BLOCK);                           // 256 threads
    dim3 grid(H_DIM / ROWS_PER_BLOCK,                         // 16 h-tiles
              C_DIM / C_PER_BLOCK,                            // 4 c-chunks
              32);                                            // B*G planes

    glrfast_kernel<<<grid, block>>>(patchs, ew, out);
}

// round 11
// speedup vs baseline: 1.0760x; 1.0655x over previous
#include <cuda_runtime.h>

// GLRFast forward: out[b,g,c,h,w] = patchs - sum_e ew[b,g,e,h,w] * nbr_e(patchs)
// nbr order (DELTAS): e0=(-1,0) up, e1=(0,-1) left, e2=(0,1) right, e3=(1,0) down
// Replicate ('edge') padding on H and W borders.
// Shapes: B=4, G=8, C=32, H=128, W=128 (fp32). node_degree (d_in[2]) unused.
//
// R10: software-pipeline 2 channels per iteration (6 back-to-back LDG.128)
// to double per-warp MLP (3 -> 6); __launch_bounds__(256,4) pins regs <= 64
// so 4 blocks (32 warps) stay resident per SM. 32 warps x 6 in-flight
// LDG.128 = ~24KB in flight per SM > the ~15KB needed to cover DRAM latency
// at ~7 TB/s.

#define H_DIM 128
#define W_DIM 128
#define C_DIM 32
#define ROWS_PER_BLOCK 8
#define C_PER_BLOCK 8

__global__ __launch_bounds__(256, 4) void glrfast_kernel(
    const float* __restrict__ patchs,
    const float* __restrict__ ew,
    float* __restrict__ out)
{
    const int lane = threadIdx.x;                         // 0..31 -> one full row per warp
    const int h    = blockIdx.x * ROWS_PER_BLOCK + threadIdx.y;
    const int c0   = blockIdx.y * C_PER_BLOCK;
    const int bg   = blockIdx.z;                          // 0..31 (= b*G + g)
    const int w0   = lane * 4;

    const int HW = H_DIM * W_DIM;

    // Edge weights for this pixel quad: [bg, e, h, w0..w0+3]
    const float* ewb = ew + ((long)bg * 4) * HW + (long)h * W_DIM + w0;
    const float4 eN = *(const float4*)(ewb + 0L * HW);
    const float4 eW = *(const float4*)(ewb + 1L * HW);
    const float4 eE = *(const float4*)(ewb + 2L * HW);
    const float4 eS = *(const float4*)(ewb + 3L * HW);

    const int hu = (h > 0)         ? h - 1 : 0;           // replicate pad
    const int hd = (h < H_DIM - 1) ? h + 1 : H_DIM - 1;

    const float* pb = patchs + ((long)bg * C_DIM + c0) * HW;
    float*       ob = out    + ((long)bg * C_DIM + c0) * HW;

    const long off_c  = (long)h  * W_DIM + w0;
    const long off_u  = (long)hu * W_DIM + w0;
    const long off_d  = (long)hd * W_DIM + w0;

#pragma unroll
    for (int cc = 0; cc < C_PER_BLOCK; cc += 2) {
        const float* pc0 = pb + (long)cc * HW;
        const float* pc1 = pc0 + HW;

        // ---- batch all 6 vector loads up front (MLP = 6) ----
        const float4 cen0 = *(const float4*)(pc0 + off_c);
        const float4 up0  = *(const float4*)(pc0 + off_u);
        const float4 dn0  = *(const float4*)(pc0 + off_d);
        const float4 cen1 = *(const float4*)(pc1 + off_c);
        const float4 up1  = *(const float4*)(pc1 + off_u);
        const float4 dn1  = *(const float4*)(pc1 + off_d);

        // ---- w-direction neighbors via in-warp shuffles (warp == one row) ----
        float xm1_0 = __shfl_up_sync(0xffffffffu, cen0.w, 1);   // x[w0-1]
        float xp4_0 = __shfl_down_sync(0xffffffffu, cen0.x, 1); // x[w0+4]
        float xm1_1 = __shfl_up_sync(0xffffffffu, cen1.w, 1);
        float xp4_1 = __shfl_down_sync(0xffffffffu, cen1.x, 1);
        if (lane == 0)  { xm1_0 = cen0.x; xm1_1 = cen1.x; }     // replicate x[0]
        if (lane == 31) { xp4_0 = cen0.w; xp4_1 = cen1.w; }     // replicate x[127]

        float4 o0, o1;
        o0.x = cen0.x - (eN.x * up0.x + eW.x * xm1_0  + eE.x * cen0.y + eS.x * dn0.x);
        o0.y = cen0.y - (eN.y * up0.y + eW.y * cen0.x + eE.y * cen0.z + eS.y * dn0.y);
        o0.z = cen0.z - (eN.z * up0.z + eW.z * cen0.y + eE.z * cen0.w + eS.z * dn0.z);
        o0.w = cen0.w - (eN.w * up0.w + eW.w * cen0.z + eE.w * xp4_0  + eS.w * dn0.w);

        o1.x = cen1.x - (eN.x * up1.x + eW.x * xm1_1  + eE.x * cen1.y + eS.x * dn1.x);
        o1.y = cen1.y - (eN.y * up1.y + eW.y * cen1.x + eE.y * cen1.z + eS.y * dn1.y);
        o1.z = cen1.z - (eN.z * up1.z + eW.z * cen1.y + eE.z * cen1.w + eS.z * dn1.z);
        o1.w = cen1.w - (eN.w * up1.w + eW.w * cen1.z + eE.w * xp4_1  + eS.w * dn1.w);

        *(float4*)(ob + (long)cc      * HW + off_c) = o0;
        *(float4*)(ob + (long)(cc + 1) * HW + off_c) = o1;
    }
}

extern "C" void kernel_launch(void* const* d_in, const int* in_sizes, int n_in,
                              void* d_out, int out_size)
{
    const float* patchs = (const float*)d_in[0];   // [4,8,32,128,128]
    const float* ew     = (const float*)d_in[1];   // [4,8,4,128,128]
    // d_in[2] = node_degree: unused in forward
    float* out = (float*)d_out;                    // [4,8,32,128,128]

    dim3 block(32, ROWS_PER_BLOCK);                           // 256 threads
    dim3 grid(H_DIM / ROWS_PER_BLOCK,                         // 16 h-tiles
              C_DIM / C_PER_BLOCK,                            // 4 c-chunks
              32);                                            // B*G planes

    glrfast_kernel<<<grid, block>>>(patchs, ew, out);
}

// round 12
// speedup vs baseline: 1.0849x; 1.0083x over previous
#include <cuda_runtime.h>

// GLRFast forward: out[b,g,c,h,w] = patchs - sum_e ew[b,g,e,h,w] * nbr_e(patchs)
// nbr order (DELTAS): e0=(-1,0) up, e1=(0,-1) left, e2=(0,1) right, e3=(1,0) down
// Replicate ('edge') padding on H and W borders.
// Shapes: B=4, G=8, C=32, H=128, W=128 (fp32). node_degree (d_in[2]) unused.
//
// R11: flat block = 4 channels, NO channel loop. 16 back-to-back LDG.128
// (4 ew + 12 patchs) front-batched per thread -> MLP_p1 = 16. 4096 small
// blocks give ~7 waves (small tail) and rapid block turnover keeps the LSU
// fed. __stcs on the output stream (evict-first) so 67MB of dirty output
// doesn't evict read lines from the 126MB L2.

#define H_DIM 128
#define W_DIM 128
#define C_DIM 32
#define ROWS_PER_BLOCK 8
#define C_PER_BLOCK 4

__global__ __launch_bounds__(256) void glrfast_kernel(
    const float* __restrict__ patchs,
    const float* __restrict__ ew,
    float* __restrict__ out)
{
    const int lane = threadIdx.x;                         // 0..31 -> one full row per warp
    const int h    = blockIdx.x * ROWS_PER_BLOCK + threadIdx.y;
    const int c0   = blockIdx.y * C_PER_BLOCK;
    const int bg   = blockIdx.z;                          // 0..31 (= b*G + g)
    const int w0   = lane * 4;

    const int HW = H_DIM * W_DIM;

    const int hu = (h > 0)         ? h - 1 : 0;           // replicate pad
    const int hd = (h < H_DIM - 1) ? h + 1 : H_DIM - 1;

    const long off_c = (long)h  * W_DIM + w0;
    const long off_u = (long)hu * W_DIM + w0;
    const long off_d = (long)hd * W_DIM + w0;

    const float* pb = patchs + ((long)bg * C_DIM + c0) * HW;
    float*       ob = out    + ((long)bg * C_DIM + c0) * HW;

    // ---- front-batch ALL loads: 4 ew + 12 patchs LDG.128, no consumers between ----
    const float* ewb = ew + ((long)bg * 4) * HW + (long)h * W_DIM + w0;
    const float4 eN = *(const float4*)(ewb + 0L * HW);
    const float4 eW = *(const float4*)(ewb + 1L * HW);
    const float4 eE = *(const float4*)(ewb + 2L * HW);
    const float4 eS = *(const float4*)(ewb + 3L * HW);

    float4 cen[C_PER_BLOCK], up[C_PER_BLOCK], dn[C_PER_BLOCK];
#pragma unroll
    for (int cc = 0; cc < C_PER_BLOCK; ++cc) {
        const float* pc = pb + (long)cc * HW;
        cen[cc] = *(const float4*)(pc + off_c);
        up[cc]  = *(const float4*)(pc + off_u);
        dn[cc]  = *(const float4*)(pc + off_d);
    }

    // ---- w-direction neighbors via in-warp shuffles (warp == one row) ----
    float xm1[C_PER_BLOCK], xp4[C_PER_BLOCK];
#pragma unroll
    for (int cc = 0; cc < C_PER_BLOCK; ++cc) {
        xm1[cc] = __shfl_up_sync(0xffffffffu, cen[cc].w, 1);   // x[w0-1]
        xp4[cc] = __shfl_down_sync(0xffffffffu, cen[cc].x, 1); // x[w0+4]
    }
    if (lane == 0) {
#pragma unroll
        for (int cc = 0; cc < C_PER_BLOCK; ++cc) xm1[cc] = cen[cc].x;   // replicate x[0]
    }
    if (lane == 31) {
#pragma unroll
        for (int cc = 0; cc < C_PER_BLOCK; ++cc) xp4[cc] = cen[cc].w;   // replicate x[127]
    }

    // ---- compute + streaming stores ----
#pragma unroll
    for (int cc = 0; cc < C_PER_BLOCK; ++cc) {
        float4 o;
        o.x = cen[cc].x - (eN.x * up[cc].x + eW.x * xm1[cc]   + eE.x * cen[cc].y + eS.x * dn[cc].x);
        o.y = cen[cc].y - (eN.y * up[cc].y + eW.y * cen[cc].x + eE.y * cen[cc].z + eS.y * dn[cc].y);
        o.z = cen[cc].z - (eN.z * up[cc].z + eW.z * cen[cc].y + eE.z * cen[cc].w + eS.z * dn[cc].z);
        o.w = cen[cc].w - (eN.w * up[cc].w + eW.w * cen[cc].z + eE.w * xp4[cc]   + eS.w * dn[cc].w);
        __stcs((float4*)(ob + (long)cc * HW + off_c), o);
    }
}

extern "C" void kernel_launch(void* const* d_in, const int* in_sizes, int n_in,
                              void* d_out, int out_size)
{
    const float* patchs = (const float*)d_in[0];   // [4,8,32,128,128]
    const float* ew     = (const float*)d_in[1];   // [4,8,4,128,128]
    // d_in[2] = node_degree: unused in forward
    float* out = (float*)d_out;                    // [4,8,32,128,128]

    dim3 block(32, ROWS_PER_BLOCK);                           // 256 threads
    dim3 grid(H_DIM / ROWS_PER_BLOCK,                         // 16 h-tiles
              C_DIM / C_PER_BLOCK,                            // 8 c-chunks
              32);                                            // B*G planes

    glrfast_kernel<<<grid, block>>>(patchs, ew, out);
}